// round 6
// baseline (speedup 1.0000x reference)
#include <cuda_runtime.h>
#include <cuda_fp16.h>
#include <cstdint>

#define Cc   256
#define Bn   8
#define Hh   128
#define Ww   128
#define NWw  512
#define HW   (Hh*Ww)
#define NPIX (Bn*HW)
#define EPSf 1e-5f

// ---- scratch ---------------------------------------------------------------
__device__ float  g_ps [Cc*Bn];
__device__ float  g_ps2[Cc*Bn];
__device__ float  g_scale[Cc];
__device__ float  g_shift[Cc];
__device__ float  g_xpad [Cc];            // -shift/scale  (pad value on raw x)
__device__ float  g_lbp2[NWw * 12];       // [j]: 9 folded weights, bias, pad2
__device__ __half g_w1h[Cc * NWw];        // [c][j] fp16 A operand

__device__ __forceinline__ uint32_t smem_u32(const void* p) {
    uint32_t a;
    asm("{ .reg .u64 t; cvta.to.shared.u64 t, %1; cvt.u32.u64 %0, t; }"
        : "=r"(a) : "l"(p));
    return a;
}

// ---------------------------------------------------------------------------
// Stats (2-stage, deterministic)
// ---------------------------------------------------------------------------
__global__ __launch_bounds__(256) void stats_part(const float* __restrict__ x) {
    int c = blockIdx.x, b = blockIdx.y, tid = threadIdx.x;
    const float4* p = (const float4*)(x + ((size_t)(b * Cc + c)) * HW);
    float s = 0.f, s2 = 0.f;
    #pragma unroll 4
    for (int i = tid; i < HW / 4; i += 256) {
        float4 v = __ldg(p + i);
        s  += v.x + v.y + v.z + v.w;
        s2 += v.x*v.x + v.y*v.y + v.z*v.z + v.w*v.w;
    }
    __shared__ float sh[256], sh2[256];
    sh[tid] = s; sh2[tid] = s2;
    __syncthreads();
    for (int off = 128; off > 0; off >>= 1) {
        if (tid < off) { sh[tid] += sh[tid+off]; sh2[tid] += sh2[tid+off]; }
        __syncthreads();
    }
    if (tid == 0) { g_ps[c*Bn + b] = sh[0]; g_ps2[c*Bn + b] = sh2[0]; }
}

__global__ void finalize_stats(const float* __restrict__ gamma,
                               const float* __restrict__ beta) {
    int c = threadIdx.x;
    float s = 0.f, s2 = 0.f;
    #pragma unroll
    for (int b = 0; b < Bn; b++) { s += g_ps[c*Bn+b]; s2 += g_ps2[c*Bn+b]; }
    float n = (float)(Bn * HW);
    float mean = s / n;
    float var  = s2 / n - mean * mean;
    float sc   = gamma[c] * rsqrtf(var + EPSf);
    g_scale[c] = sc;
    g_shift[c] = beta[c] - mean * sc;
    g_xpad[c]  = -(beta[c] - mean * sc) / sc;
}

// fold BN into stencil weights: y_j = sum_t (w*sc) x + shift*sum_t w
__global__ void prep_lbp(const float* __restrict__ lbp) {
    int j  = threadIdx.x;                 // 512 threads, 1 block
    int ci = j >> 1;
    float sc = g_scale[ci], sf = g_shift[ci];
    float s = 0.f;
    #pragma unroll
    for (int t = 0; t < 9; t++) {
        float w = __ldg(lbp + j * 9 + t);
        g_lbp2[j * 12 + t] = w * sc;
        s += w;
    }
    g_lbp2[j * 12 + 9]  = sf * s;
    g_lbp2[j * 12 + 10] = 0.f;
    g_lbp2[j * 12 + 11] = 0.f;
}

__global__ void w1half(const float* __restrict__ w1) {
    int i = blockIdx.x * 256 + threadIdx.x;
    g_w1h[i] = __float2half_rn(w1[i]);
}

// ---------------------------------------------------------------------------
// Fused kernel: per block = one output row (h, b); M=256 ch x N=128 pixels.
// K = 512 j in 32 chunks of (8 in-ch -> 16 j).
// Stages (double-buffered):
//   XS: raw x, 8ch x 3rows x 136 floats (data at [4..131], pads [3],[132])
//   A : w1h   256 rows x 48B (32B data: 16 halves)
//   Y : dw out 128 rows x 48B (32B data: 16 halves)
//   LW: folded weights 16 x 12 floats
// ---------------------------------------------------------------------------
#define XS_ST 13056
#define A_ST  12288
#define Y_ST  6144
#define LW_ST 768
#define OFF_XS(s) ((s) * XS_ST)
#define OFF_A(s)  (2*XS_ST + (s) * A_ST)
#define OFF_Y(s)  (2*XS_ST + 2*A_ST + (s) * Y_ST)
#define OFF_LW(s) (2*XS_ST + 2*A_ST + 2*Y_ST + (s) * LW_ST)
#define SMEM_TOT  (2*XS_ST + 2*A_ST + 2*Y_ST + 2*LW_ST)   // 64512

__global__ __launch_bounds__(512, 1)
void fused_kernel(const float* __restrict__ x, const float* __restrict__ b1,
                  float* __restrict__ out) {
    extern __shared__ __align__(1024) char dsm[];
    const uint32_t s0 = smem_u32(dsm);

    const int tid  = threadIdx.x;
    const int wid  = tid >> 5, lane = tid & 31;
    const int wm   = wid >> 2;                 // 0..3 (M)
    const int wn   = wid & 3;                  // 0..3 (N)
    const int h    = blockIdx.x;
    const int b    = blockIdx.y;

    float acc[4][4][4];
    #pragma unroll
    for (int mi = 0; mi < 4; mi++)
        #pragma unroll
        for (int ni = 0; ni < 4; ni++)
            #pragma unroll
            for (int q = 0; q < 4; q++) acc[mi][ni][q] = 0.f;

    // stencil thread mapping: jp = channel-local (0..7), ppair (0..63)
    const int jp   = lane & 7;
    const int pp2  = (wid << 2) + (lane >> 3); // 0..63
    const int p0c  = pp2 * 2;

    const int oobr = (h == 0) ? 0 : ((h == Hh - 1) ? 2 : -1);

    // ---- async fill of stage st with chunk kc ----
    auto fill = [&](int st, int kc) {
        const int cb8 = kc * 8;
        // x: 8ch x 3rows x 32 float4
        #pragma unroll
        for (int i = 0; i < 2; i++) {
            int idx = tid + i * 512;
            if (idx < 768) {
                int ci  = idx / 96;
                int rem = idx - ci * 96;
                int r   = rem >> 5, q = rem & 31;
                int hh  = h - 1 + r;
                int ok  = ((unsigned)hh < (unsigned)Hh) ? 16 : 0;
                int hcl = ok ? hh : 0;
                const float* src =
                    x + ((size_t)(b * Cc + cb8 + ci)) * HW + hcl * Ww + q * 4;
                uint32_t dst = s0 + OFF_XS(st) + (ci * 408 + r * 136 + 4 + q * 4) * 4;
                asm volatile("cp.async.cg.shared.global [%0], [%1], 16, %2;"
                             :: "r"(dst), "l"(src), "r"(ok));
            }
        }
        // A: 256 rows x 2 x 16B
        {
            int row = tid >> 1, u = tid & 1;
            const __half* src = g_w1h + (size_t)row * NWw + kc * 16 + u * 8;
            uint32_t dst = s0 + OFF_A(st) + row * 48 + u * 16;
            asm volatile("cp.async.cg.shared.global [%0], [%1], 16;"
                         :: "r"(dst), "l"(src));
        }
        // LW: 48 x 16B
        if (tid < 48) {
            const float* src = g_lbp2 + kc * 192 + tid * 4;
            uint32_t dst = s0 + OFF_LW(st) + tid * 16;
            asm volatile("cp.async.cg.shared.global [%0], [%1], 16;"
                         :: "r"(dst), "l"(src));
        }
        asm volatile("cp.async.commit_group;");
    };

    fill(0, 0);

    for (int kc = 0; kc < 32; kc++) {
        const int st = kc & 1;
        const int cb8 = kc * 8;
        asm volatile("cp.async.wait_group 0;");

        // pad columns with xpad (cancels folded bias for OOB taps)
        float* xsf = (float*)(dsm + OFF_XS(st));
        if (tid < 48) {
            int ci = tid / 6, rem = tid - ci * 6;
            int rr = rem >> 1, side = rem & 1;
            float xp = __ldg(g_xpad + cb8 + ci);
            xsf[ci * 408 + rr * 136 + (side ? 132 : 3)] = xp;
        }
        if (oobr >= 0) {
            #pragma unroll
            for (int i = 0; i < 3; i++) {
                int idx = tid + i * 512;
                if (idx < 1040) {
                    int ci = idx / 130, col = idx - ci * 130 + 3;
                    xsf[ci * 408 + oobr * 136 + col] = __ldg(g_xpad + cb8 + ci);
                }
            }
        }
        __syncthreads();   // fills + pads visible; prev HMMA done with old bufs

        if (kc < 31) fill(st ^ 1, kc + 1);

        // ---- stencil: 4 outputs (2 j x 2 pixels) per thread ----
        {
            const float* lws = (const float*)(dsm + OFF_LW(st)) + jp * 24;
            const float* xc  = xsf + jp * 408 + 3 + p0c;
            float t0[4], t1[4], t2[4];
            #pragma unroll
            for (int k = 0; k < 4; k++) {
                t0[k] = xc[k];
                t1[k] = xc[136 + k];
                t2[k] = xc[272 + k];
            }
            float y00 = lws[9],  y01 = lws[21];
            float y10 = lws[9],  y11 = lws[21];
            #pragma unroll
            for (int k = 0; k < 3; k++) {
                float w0a = lws[k],      w0b = lws[3 + k],  w0c = lws[6 + k];
                float w1a = lws[12 + k], w1b = lws[15 + k], w1c = lws[18 + k];
                y00 = fmaf(w0a, t0[k],     y00);
                y10 = fmaf(w0a, t0[k + 1], y10);
                y01 = fmaf(w1a, t0[k],     y01);
                y11 = fmaf(w1a, t0[k + 1], y11);
                y00 = fmaf(w0b, t1[k],     y00);
                y10 = fmaf(w0b, t1[k + 1], y10);
                y01 = fmaf(w1b, t1[k],     y01);
                y11 = fmaf(w1b, t1[k + 1], y11);
                y00 = fmaf(w0c, t2[k],     y00);
                y10 = fmaf(w0c, t2[k + 1], y10);
                y01 = fmaf(w1c, t2[k],     y01);
                y11 = fmaf(w1c, t2[k + 1], y11);
            }
            __half2 h0 = __floats2half2_rn(fmaxf(y00, 0.f), fmaxf(y01, 0.f));
            __half2 h1 = __floats2half2_rn(fmaxf(y10, 0.f), fmaxf(y11, 0.f));
            char* yb = dsm + OFF_Y(st);
            *(uint32_t*)(yb + p0c * 48 + jp * 4)       = *(uint32_t*)&h0;
            *(uint32_t*)(yb + (p0c + 1) * 48 + jp * 4) = *(uint32_t*)&h1;
        }
        __syncthreads();   // y visible

        // ---- HMMA on chunk (K=16) ----
        {
            const uint32_t sA = s0 + OFF_A(st);
            const uint32_t sY = s0 + OFF_Y(st);
            uint32_t a[4][4], bf[4][2];
            #pragma unroll
            for (int mi = 0; mi < 4; mi++) {
                int row = wm * 64 + mi * 16 + (lane & 15);
                uint32_t ad = sA + row * 48 + (lane >> 4) * 16;
                asm volatile(
                    "ldmatrix.sync.aligned.m8n8.x4.shared.b16 {%0,%1,%2,%3}, [%4];"
                    : "=r"(a[mi][0]), "=r"(a[mi][1]), "=r"(a[mi][2]), "=r"(a[mi][3])
                    : "r"(ad));
            }
            #pragma unroll
            for (int ni = 0; ni < 4; ni++) {
                int row = wn * 32 + ni * 8 + (lane & 7);
                uint32_t bd = sY + row * 48 + ((lane >> 3) & 1) * 16;
                asm volatile(
                    "ldmatrix.sync.aligned.m8n8.x2.shared.b16 {%0,%1}, [%2];"
                    : "=r"(bf[ni][0]), "=r"(bf[ni][1]) : "r"(bd));
            }
            #pragma unroll
            for (int mi = 0; mi < 4; mi++)
                #pragma unroll
                for (int ni = 0; ni < 4; ni++)
                    asm volatile(
                        "mma.sync.aligned.m16n8k16.row.col.f32.f16.f16.f32 "
                        "{%0,%1,%2,%3}, {%4,%5,%6,%7}, {%8,%9}, {%0,%1,%2,%3};"
                        : "+f"(acc[mi][ni][0]), "+f"(acc[mi][ni][1]),
                          "+f"(acc[mi][ni][2]), "+f"(acc[mi][ni][3])
                        : "r"(a[mi][0]), "r"(a[mi][1]), "r"(a[mi][2]), "r"(a[mi][3]),
                          "r"(bf[ni][0]), "r"(bf[ni][1]));
        }
        __syncthreads();   // HMMA reads done before next overwrite
    }

    // ---- epilogue: + b1[c] + x residual ----
    const int colb = wn * 32 + (lane & 3) * 2;
    #pragma unroll
    for (int mi = 0; mi < 4; mi++) {
        int cb = wm * 64 + mi * 16 + (lane >> 2);
        #pragma unroll
        for (int hh = 0; hh < 2; hh++) {
            int c = cb + hh * 8;
            float bias = __ldg(b1 + c);
            size_t base = ((size_t)(b * Cc + c)) * HW + h * Ww + colb;
            #pragma unroll
            for (int ni = 0; ni < 4; ni++) {
                size_t o = base + ni * 8;
                float2 xv = *(const float2*)(x + o);
                float2 r;
                r.x = acc[mi][ni][hh * 2 + 0] + bias + xv.x;
                r.y = acc[mi][ni][hh * 2 + 1] + bias + xv.y;
                *(float2*)(out + o) = r;
            }
        }
    }
}

// ---------------------------------------------------------------------------
extern "C" void kernel_launch(void* const* d_in, const int* in_sizes, int n_in,
                              void* d_out, int out_size) {
    const float* x     = (const float*)d_in[0];
    const float* gamma = (const float*)d_in[1];
    const float* beta  = (const float*)d_in[2];
    const float* lbp   = (const float*)d_in[3];
    const float* w1    = (const float*)d_in[4];
    const float* b1    = (const float*)d_in[5];
    float* out = (float*)d_out;

    static bool attr_done = false;
    if (!attr_done) {
        cudaFuncSetAttribute(fused_kernel,
                             cudaFuncAttributeMaxDynamicSharedMemorySize,
                             SMEM_TOT);
        attr_done = true;
    }

    stats_part<<<dim3(Cc, Bn), 256>>>(x);
    finalize_stats<<<1, Cc>>>(gamma, beta);
    prep_lbp<<<1, NWw>>>(lbp);
    w1half<<<(Cc * NWw) / 256, 256>>>(w1);
    fused_kernel<<<dim3(Hh, Bn), 512, SMEM_TOT>>>(x, b1, out);
}

// round 7
// speedup vs baseline: 1.9208x; 1.9208x over previous
#include <cuda_runtime.h>
#include <cuda_fp16.h>
#include <cstdint>

#define Cc   256
#define Bn   8
#define Hh   128
#define Ww   128
#define NWw  512
#define HW   (Hh*Ww)
#define NPIX (Bn*HW)
#define EPSf 1e-5f

// ---- scratch ---------------------------------------------------------------
__device__ float  g_ps [Cc*Bn];
__device__ float  g_ps2[Cc*Bn];
__device__ float  g_scale[Cc];
__device__ float  g_shift[Cc];
__device__ __half g_w1h[Cc * NWw];               // [c][j]  A operand (K-major)
__device__ __half g_y2[(size_t)NWw * NPIX];      // [j][pixel]  B operand

__device__ __forceinline__ uint32_t smem_u32(const void* p) {
    uint32_t a;
    asm("{ .reg .u64 t; cvta.to.shared.u64 t, %1; cvt.u32.u64 %0, t; }"
        : "=r"(a) : "l"(p));
    return a;
}

// ---------------------------------------------------------------------------
// Stats (2-stage, deterministic)
// ---------------------------------------------------------------------------
__global__ __launch_bounds__(256) void stats_part(const float* __restrict__ x) {
    int c = blockIdx.x, b = blockIdx.y, tid = threadIdx.x;
    const float4* p = (const float4*)(x + ((size_t)(b * Cc + c)) * HW);
    float s = 0.f, s2 = 0.f;
    #pragma unroll 4
    for (int i = tid; i < HW / 4; i += 256) {
        float4 v = __ldg(p + i);
        s  += v.x + v.y + v.z + v.w;
        s2 += v.x*v.x + v.y*v.y + v.z*v.z + v.w*v.w;
    }
    __shared__ float sh[256], sh2[256];
    sh[tid] = s; sh2[tid] = s2;
    __syncthreads();
    for (int off = 128; off > 0; off >>= 1) {
        if (tid < off) { sh[tid] += sh[tid+off]; sh2[tid] += sh2[tid+off]; }
        __syncthreads();
    }
    if (tid == 0) { g_ps[c*Bn + b] = sh[0]; g_ps2[c*Bn + b] = sh2[0]; }
}

__global__ void finalize_stats(const float* __restrict__ gamma,
                               const float* __restrict__ beta) {
    int c = threadIdx.x;
    float s = 0.f, s2 = 0.f;
    #pragma unroll
    for (int b = 0; b < Bn; b++) { s += g_ps[c*Bn+b]; s2 += g_ps2[c*Bn+b]; }
    float n = (float)(Bn * HW);
    float mean = s / n;
    float var  = s2 / n - mean * mean;
    float sc   = gamma[c] * rsqrtf(var + EPSf);
    g_scale[c] = sc;
    g_shift[c] = beta[c] - mean * sc;
}

__global__ void w1half(const float* __restrict__ w1) {
    int i = (blockIdx.x * 256 + threadIdx.x) * 4;
    float4 v = __ldg((const float4*)(w1 + i));
    __half2 a = __floats2half2_rn(v.x, v.y);
    __half2 b = __floats2half2_rn(v.z, v.w);
    uint2 o = make_uint2(*(uint32_t*)&a, *(uint32_t*)&b);
    *(uint2*)(g_w1h + i) = o;
}

// ---------------------------------------------------------------------------
// Kernel 2 (v4): BN -> depthwise 3x3 -> relu -> fp16 y2[j][pixel]
// Block: 8 input channels (16 j) x 8-row strip x 128 cols, 256 threads.
// Per cidx: stencil (1 px, 2 j per thread, rotating rows) -> stage 4 j rows
// in smem -> wide contiguous stores to y2.
// smem: xs[8][10][136] f32 | lw[16][9] f32 | sy[4][8][128] f16  = 52288 B
// ---------------------------------------------------------------------------
#define DW_SMEM (43520 + 576 + 8192)

__global__ __launch_bounds__(256, 3)
void dw_kernel(const float* __restrict__ x, const float* __restrict__ lbp) {
    extern __shared__ __align__(16) char dsm[];
    float*  xs = (float*)dsm;                  // [8][10][136]
    float*  lw = (float*)(dsm + 43520);        // [16][9]
    __half* sy = (__half*)(dsm + 44096);       // [4][8][128]

    const int tid   = threadIdx.x;
    const int chunk = blockIdx.x;              // 0..31
    const int h0    = blockIdx.y * 8;
    const int b     = blockIdx.z;
    const int cbase = chunk * 8;
    const int jbase = chunk * 16;

    // zero pad columns ([3] and [132] of each row)
    if (tid < 80) {
        int ci = tid / 10, rr = tid - ci * 10;
        xs[ci * 1360 + rr * 136 + 3]   = 0.f;
        xs[ci * 1360 + rr * 136 + 132] = 0.f;
    }
    if (tid < 144) lw[tid] = __ldg(lbp + jbase * 9 + tid);

    // main tile: 8 ch x 10 rows x 32 float4, normalized (OOB rows -> 0)
    #pragma unroll
    for (int ci = 0; ci < 8; ci++) {
        const float sc = g_scale[cbase + ci];
        const float sf = g_shift[cbase + ci];
        const float4* src =
            (const float4*)(x + ((size_t)(b * Cc + cbase + ci)) * HW);
        #pragma unroll
        for (int i = 0; i < 2; i++) {
            int idx = tid + i * 256;
            if (idx < 320) {
                int rr = idx >> 5, q = idx & 31;
                int hh = h0 - 1 + rr;
                float4 w = make_float4(0.f, 0.f, 0.f, 0.f);
                if ((unsigned)hh < (unsigned)Hh) {
                    float4 v = __ldg(src + hh * 32 + q);
                    w.x = fmaf(v.x, sc, sf);
                    w.y = fmaf(v.y, sc, sf);
                    w.z = fmaf(v.z, sc, sf);
                    w.w = fmaf(v.w, sc, sf);
                }
                *(float4*)&xs[ci * 1360 + rr * 136 + 4 + 4 * q] = w;
            }
        }
    }
    __syncthreads();

    const int p  = tid & 127;
    const int jh = tid >> 7;
    const size_t bHW = (size_t)b * HW;

    #pragma unroll
    for (int cidx = 0; cidx < 4; cidx++) {
        const int ci = jh * 4 + cidx;
        const int jl = ci * 2;
        float w0[9], w1w[9];
        #pragma unroll
        for (int t = 0; t < 9; t++) {
            w0[t]  = lw[jl * 9 + t];
            w1w[t] = lw[(jl + 1) * 9 + t];
        }
        const float* xr = xs + ci * 1360;
        float a0 = xr[3 + p],       a1 = xr[4 + p],       a2 = xr[5 + p];
        float b0 = xr[139 + p],     b1v = xr[140 + p],    b2 = xr[141 + p];
        __half* s0p = sy + (jh * 2) * 1024 + p;
        __half* s1p = s0p + 1024;
        #pragma unroll
        for (int r = 0; r < 8; r++) {
            const float* rc = xr + (r + 2) * 136 + p;
            float c0 = rc[3], c1 = rc[4], c2 = rc[5];
            float s0, s1;
            s0 = w0[0]*a0;            s1 = w1w[0]*a0;
            s0 = fmaf(w0[1],a1,s0);   s1 = fmaf(w1w[1],a1,s1);
            s0 = fmaf(w0[2],a2,s0);   s1 = fmaf(w1w[2],a2,s1);
            s0 = fmaf(w0[3],b0,s0);   s1 = fmaf(w1w[3],b0,s1);
            s0 = fmaf(w0[4],b1v,s0);  s1 = fmaf(w1w[4],b1v,s1);
            s0 = fmaf(w0[5],b2,s0);   s1 = fmaf(w1w[5],b2,s1);
            s0 = fmaf(w0[6],c0,s0);   s1 = fmaf(w1w[6],c0,s1);
            s0 = fmaf(w0[7],c1,s0);   s1 = fmaf(w1w[7],c1,s1);
            s0 = fmaf(w0[8],c2,s0);   s1 = fmaf(w1w[8],c2,s1);
            s0p[r * 128] = __float2half_rn(fmaxf(s0, 0.f));
            s1p[r * 128] = __float2half_rn(fmaxf(s1, 0.f));
            a0 = b0; a1 = b1v; a2 = b2;
            b0 = c0; b1v = c1; b2 = c2;
        }
        __syncthreads();

        // store out: 4 j x 8 rows x 16 pixel-groups of 8 -> 512 uint4
        #pragma unroll
        for (int i = 0; i < 2; i++) {
            int idx = tid + i * 256;
            int s  = idx >> 7;             // 0..3: jh'*2 + j2
            int r  = (idx >> 4) & 7;
            int pg = idx & 15;
            uint4 v = *(uint4*)(sy + s * 1024 + r * 128 + pg * 8);
            int jglob = jbase + (s >> 1) * 8 + cidx * 2 + (s & 1);
            *(uint4*)(g_y2 + (size_t)jglob * NPIX + bHW
                      + (h0 + r) * Ww + pg * 8) = v;
        }
        __syncthreads();
    }
}

// ---------------------------------------------------------------------------
// Kernel 3: HMMA GEMM (round-4 config = HMMA floor), B from y2[j][pixel]
// Block tile 128(M) x 128(N), K=512 in 8 chunks of 64; 8 warps (2x4), 64x32.
// A tile: 128 rows x 128B (K-major).  B tile: 64 k-rows x 256B (N-major),
// consumed via ldmatrix.x2.trans.
// ---------------------------------------------------------------------------
#define STG_BYTES 32768   // per stage: A 16KB + B 16KB

__global__ __launch_bounds__(256)
void gemm_kernel(const float* __restrict__ x, const float* __restrict__ b1,
                 float* __restrict__ out) {
    extern __shared__ __align__(1024) char dsm[];
    const uint32_t s0 = smem_u32(dsm);

    const int tid  = threadIdx.x;
    const int wid  = tid >> 5, lane = tid & 31;
    const int wm   = wid & 1;
    const int wn   = wid >> 1;
    const int mt   = blockIdx.x;
    const size_t p0 = (size_t)blockIdx.y * 128;

    float acc[4][4][4];
    #pragma unroll
    for (int mi = 0; mi < 4; mi++)
        #pragma unroll
        for (int ni = 0; ni < 4; ni++)
            #pragma unroll
            for (int q = 0; q < 4; q++) acc[mi][ni][q] = 0.f;

    const __half* wsrc = g_w1h + (size_t)mt * 128 * NWw;
    const int lrow = tid >> 3, lu = tid & 7;     // A fill coords
    const int bkr  = tid >> 4, bu = tid & 15;    // B fill coords

    auto fill = [&](int st, int kc) {
        const uint32_t sA = s0 + st * STG_BYTES;
        const uint32_t sB = sA + 16384;
        const int k0 = kc * 64;
        #pragma unroll
        for (int i = 0; i < 4; i++) {            // A: 128 rows x 8 x 16B
            int row = lrow + i * 32;
            uint32_t sw = ((lu ^ (row & 7)) << 4) + row * 128;
            const __half* srcA = wsrc + (size_t)row * NWw + k0 + lu * 8;
            asm volatile("cp.async.cg.shared.global [%0], [%1], 16;"
                         :: "r"(sA + sw), "l"(srcA));
        }
        #pragma unroll
        for (int i = 0; i < 4; i++) {            // B: 64 k-rows x 16 x 16B
            int kr = bkr + i * 16;
            uint32_t dst = sB + kr * 256 + ((bu ^ (kr & 7)) << 4);
            const __half* srcB =
                g_y2 + (size_t)(k0 + kr) * NPIX + p0 + bu * 8;
            asm volatile("cp.async.cg.shared.global [%0], [%1], 16;"
                         :: "r"(dst), "l"(srcB));
        }
        asm volatile("cp.async.commit_group;");
    };

    fill(0, 0);
    for (int kc = 0; kc < 8; kc++) {
        if (kc < 7) fill((kc + 1) & 1, kc + 1);
        if (kc < 7) asm volatile("cp.async.wait_group 1;");
        else        asm volatile("cp.async.wait_group 0;");
        __syncthreads();

        const uint32_t sA = s0 + (kc & 1) * STG_BYTES;
        const uint32_t sB = sA + 16384;

        #pragma unroll
        for (int ks = 0; ks < 4; ks++) {
            uint32_t a[4][4], bf[4][2];
            #pragma unroll
            for (int mi = 0; mi < 4; mi++) {
                int row = wm * 64 + mi * 16 + (lane & 15);
                uint32_t ad = sA + row * 128 + (((ks * 2 + (lane >> 4)) ^ (row & 7)) << 4);
                asm volatile(
                    "ldmatrix.sync.aligned.m8n8.x4.shared.b16 {%0,%1,%2,%3}, [%4];"
                    : "=r"(a[mi][0]), "=r"(a[mi][1]), "=r"(a[mi][2]), "=r"(a[mi][3])
                    : "r"(ad));
            }
            #pragma unroll
            for (int ni = 0; ni < 4; ni++) {
                int kr = ks * 16 + (lane & 15);
                uint32_t uu = wn * 4 + ni;
                uint32_t bd = sB + kr * 256 + ((uu ^ (kr & 7)) << 4);
                asm volatile(
                    "ldmatrix.sync.aligned.m8n8.x2.trans.shared.b16 {%0,%1}, [%2];"
                    : "=r"(bf[ni][0]), "=r"(bf[ni][1]) : "r"(bd));
            }
            #pragma unroll
            for (int mi = 0; mi < 4; mi++)
                #pragma unroll
                for (int ni = 0; ni < 4; ni++)
                    asm volatile(
                        "mma.sync.aligned.m16n8k16.row.col.f32.f16.f16.f32 "
                        "{%0,%1,%2,%3}, {%4,%5,%6,%7}, {%8,%9}, {%0,%1,%2,%3};"
                        : "+f"(acc[mi][ni][0]), "+f"(acc[mi][ni][1]),
                          "+f"(acc[mi][ni][2]), "+f"(acc[mi][ni][3])
                        : "r"(a[mi][0]), "r"(a[mi][1]), "r"(a[mi][2]), "r"(a[mi][3]),
                          "r"(bf[ni][0]), "r"(bf[ni][1]));
        }
        __syncthreads();
    }

    // epilogue: + b1[c] + x residual
    const int bb  = (int)(p0 >> 14);
    const int hw0 = (int)(p0 & 16383) + wn * 32 + (lane & 3) * 2;
    #pragma unroll
    for (int mi = 0; mi < 4; mi++) {
        int cb = mt * 128 + wm * 64 + mi * 16 + (lane >> 2);
        #pragma unroll
        for (int h = 0; h < 2; h++) {
            int c = cb + h * 8;
            float bias = __ldg(b1 + c);
            size_t base = ((size_t)(bb * Cc + c)) * HW + hw0;
            #pragma unroll
            for (int ni = 0; ni < 4; ni++) {
                size_t o = base + ni * 8;
                float2 xv = *(const float2*)(x + o);
                float2 r;
                r.x = acc[mi][ni][h * 2 + 0] + bias + xv.x;
                r.y = acc[mi][ni][h * 2 + 1] + bias + xv.y;
                *(float2*)(out + o) = r;
            }
        }
    }
}

// ---------------------------------------------------------------------------
extern "C" void kernel_launch(void* const* d_in, const int* in_sizes, int n_in,
                              void* d_out, int out_size) {
    const float* x     = (const float*)d_in[0];
    const float* gamma = (const float*)d_in[1];
    const float* beta  = (const float*)d_in[2];
    const float* lbp   = (const float*)d_in[3];
    const float* w1    = (const float*)d_in[4];
    const float* b1    = (const float*)d_in[5];
    float* out = (float*)d_out;

    static bool attr_done = false;
    if (!attr_done) {
        cudaFuncSetAttribute(gemm_kernel,
                             cudaFuncAttributeMaxDynamicSharedMemorySize,
                             2 * STG_BYTES);
        cudaFuncSetAttribute(dw_kernel,
                             cudaFuncAttributeMaxDynamicSharedMemorySize,
                             DW_SMEM);
        attr_done = true;
    }

    stats_part<<<dim3(Cc, Bn), 256>>>(x);
    finalize_stats<<<1, Cc>>>(gamma, beta);
    w1half<<<(Cc * NWw) / 1024, 256>>>(w1);
    dw_kernel<<<dim3(32, 16, Bn), 256, DW_SMEM>>>(x, lbp);
    gemm_kernel<<<dim3(2, NPIX / 128), 256, 2 * STG_BYTES>>>(x, b1, out);
}

// round 8
// speedup vs baseline: 1.9501x; 1.0153x over previous
#include <cuda_runtime.h>
#include <cuda_fp16.h>
#include <cstdint>

#define Cc   256
#define Bn   8
#define Hh   128
#define Ww   128
#define NWw  512
#define HW   (Hh*Ww)
#define NPIX (Bn*HW)
#define EPSf 1e-5f

// ---- scratch ---------------------------------------------------------------
__device__ float  g_ps [Cc*Bn];
__device__ float  g_ps2[Cc*Bn];
__device__ float  g_scale[Cc];
__device__ float  g_shift[Cc];
__device__ __half g_w1h[Cc * NWw];               // [c][j]  A operand (K-major)
__device__ __half g_y2[(size_t)NWw * NPIX];      // [j][pixel]  B operand

__device__ __forceinline__ uint32_t smem_u32(const void* p) {
    uint32_t a;
    asm("{ .reg .u64 t; cvta.to.shared.u64 t, %1; cvt.u32.u64 %0, t; }"
        : "=r"(a) : "l"(p));
    return a;
}

// ---------------------------------------------------------------------------
// Stats (2-stage, deterministic)
// ---------------------------------------------------------------------------
__global__ __launch_bounds__(256) void stats_part(const float* __restrict__ x) {
    int c = blockIdx.x, b = blockIdx.y, tid = threadIdx.x;
    const float4* p = (const float4*)(x + ((size_t)(b * Cc + c)) * HW);
    float s = 0.f, s2 = 0.f;
    #pragma unroll 4
    for (int i = tid; i < HW / 4; i += 256) {
        float4 v = __ldg(p + i);
        s  += v.x + v.y + v.z + v.w;
        s2 += v.x*v.x + v.y*v.y + v.z*v.z + v.w*v.w;
    }
    __shared__ float sh[256], sh2[256];
    sh[tid] = s; sh2[tid] = s2;
    __syncthreads();
    for (int off = 128; off > 0; off >>= 1) {
        if (tid < off) { sh[tid] += sh[tid+off]; sh2[tid] += sh2[tid+off]; }
        __syncthreads();
    }
    if (tid == 0) { g_ps[c*Bn + b] = sh[0]; g_ps2[c*Bn + b] = sh2[0]; }
}

__global__ void finalize_stats(const float* __restrict__ gamma,
                               const float* __restrict__ beta) {
    int c = threadIdx.x;
    float s = 0.f, s2 = 0.f;
    #pragma unroll
    for (int b = 0; b < Bn; b++) { s += g_ps[c*Bn+b]; s2 += g_ps2[c*Bn+b]; }
    float n = (float)(Bn * HW);
    float mean = s / n;
    float var  = s2 / n - mean * mean;
    float sc   = gamma[c] * rsqrtf(var + EPSf);
    g_scale[c] = sc;
    g_shift[c] = beta[c] - mean * sc;
}

__global__ void w1half(const float* __restrict__ w1) {
    int i = (blockIdx.x * 256 + threadIdx.x) * 4;
    float4 v = __ldg((const float4*)(w1 + i));
    __half2 a = __floats2half2_rn(v.x, v.y);
    __half2 b = __floats2half2_rn(v.z, v.w);
    uint2 o = make_uint2(*(uint32_t*)&a, *(uint32_t*)&b);
    *(uint2*)(g_w1h + i) = o;
}

// ---------------------------------------------------------------------------
// Kernel 2 (v5): BN -> depthwise 3x3 -> relu -> fp16 y2[j][pixel]
// Block: 8 input channels (16 j) x 8-row strip x 128 cols, 256 threads.
// No staging buffer: direct STG.U16 stores (warp = 64B contiguous). No
// per-chunk syncs. 4 CTAs/SM.
// ---------------------------------------------------------------------------
__global__ __launch_bounds__(256, 4)
void dw_kernel(const float* __restrict__ x, const float* __restrict__ lbp) {
    __shared__ float xs[8][10][136];           // 43520 B
    __shared__ float lw[16][9];

    const int tid   = threadIdx.x;
    const int chunk = blockIdx.x;              // 0..31
    const int h0    = blockIdx.y * 8;
    const int b     = blockIdx.z;
    const int cbase = chunk * 8;
    const int jbase = chunk * 16;

    // zero pad columns ([3] and [132] of each row)
    if (tid < 80) {
        int ci = tid / 10, rr = tid - ci * 10;
        xs[ci][rr][3]   = 0.f;
        xs[ci][rr][132] = 0.f;
    }
    if (tid < 144) ((float*)lw)[tid] = __ldg(lbp + jbase * 9 + tid);

    // main tile: 8 ch x 10 rows x 32 float4, normalized (OOB rows -> 0)
    #pragma unroll
    for (int ci = 0; ci < 8; ci++) {
        const float sc = g_scale[cbase + ci];
        const float sf = g_shift[cbase + ci];
        const float4* src =
            (const float4*)(x + ((size_t)(b * Cc + cbase + ci)) * HW);
        #pragma unroll
        for (int i = 0; i < 2; i++) {
            int idx = tid + i * 256;
            if (idx < 320) {
                int rr = idx >> 5, q = idx & 31;
                int hh = h0 - 1 + rr;
                float4 w = make_float4(0.f, 0.f, 0.f, 0.f);
                if ((unsigned)hh < (unsigned)Hh) {
                    float4 v = __ldg(src + hh * 32 + q);
                    w.x = fmaf(v.x, sc, sf);
                    w.y = fmaf(v.y, sc, sf);
                    w.z = fmaf(v.z, sc, sf);
                    w.w = fmaf(v.w, sc, sf);
                }
                *(float4*)&xs[ci][rr][4 + 4 * q] = w;
            }
        }
    }
    __syncthreads();

    const int p  = tid & 127;
    const int jh = tid >> 7;
    const size_t rowbase = (size_t)b * HW + (size_t)h0 * Ww + p;

    #pragma unroll
    for (int cidx = 0; cidx < 4; cidx++) {
        const int ci = jh * 4 + cidx;
        const int jl = ci * 2;
        float w0[9], w1w[9];
        #pragma unroll
        for (int t = 0; t < 9; t++) {
            w0[t]  = lw[jl][t];
            w1w[t] = lw[jl + 1][t];
        }
        const float* xr = &xs[ci][0][0];
        float a0 = xr[3 + p],   a1 = xr[4 + p],   a2 = xr[5 + p];
        float b0 = xr[139 + p], b1v = xr[140 + p], b2 = xr[141 + p];
        __half* y0p = g_y2 + (size_t)(jbase + jl) * NPIX + rowbase;
        __half* y1p = y0p + NPIX;
        #pragma unroll
        for (int r = 0; r < 8; r++) {
            const float* rc = xr + (r + 2) * 136 + p;
            float c0 = rc[3], c1 = rc[4], c2 = rc[5];
            float s0, s1;
            s0 = w0[0]*a0;            s1 = w1w[0]*a0;
            s0 = fmaf(w0[1],a1,s0);   s1 = fmaf(w1w[1],a1,s1);
            s0 = fmaf(w0[2],a2,s0);   s1 = fmaf(w1w[2],a2,s1);
            s0 = fmaf(w0[3],b0,s0);   s1 = fmaf(w1w[3],b0,s1);
            s0 = fmaf(w0[4],b1v,s0);  s1 = fmaf(w1w[4],b1v,s1);
            s0 = fmaf(w0[5],b2,s0);   s1 = fmaf(w1w[5],b2,s1);
            s0 = fmaf(w0[6],c0,s0);   s1 = fmaf(w1w[6],c0,s1);
            s0 = fmaf(w0[7],c1,s0);   s1 = fmaf(w1w[7],c1,s1);
            s0 = fmaf(w0[8],c2,s0);   s1 = fmaf(w1w[8],c2,s1);
            y0p[r * Ww] = __float2half_rn(fmaxf(s0, 0.f));
            y1p[r * Ww] = __float2half_rn(fmaxf(s1, 0.f));
            a0 = b0; a1 = b1v; a2 = b2;
            b0 = c0; b1v = c1; b2 = c2;
        }
    }
}

// ---------------------------------------------------------------------------
// Kernel 3: HMMA GEMM (unchanged — at HMMA floor), B from y2[j][pixel]
// ---------------------------------------------------------------------------
#define STG_BYTES 32768   // per stage: A 16KB + B 16KB

__global__ __launch_bounds__(256)
void gemm_kernel(const float* __restrict__ x, const float* __restrict__ b1,
                 float* __restrict__ out) {
    extern __shared__ __align__(1024) char dsm[];
    const uint32_t s0 = smem_u32(dsm);

    const int tid  = threadIdx.x;
    const int wid  = tid >> 5, lane = tid & 31;
    const int wm   = wid & 1;
    const int wn   = wid >> 1;
    const int mt   = blockIdx.x;
    const size_t p0 = (size_t)blockIdx.y * 128;

    float acc[4][4][4];
    #pragma unroll
    for (int mi = 0; mi < 4; mi++)
        #pragma unroll
        for (int ni = 0; ni < 4; ni++)
            #pragma unroll
            for (int q = 0; q < 4; q++) acc[mi][ni][q] = 0.f;

    const __half* wsrc = g_w1h + (size_t)mt * 128 * NWw;
    const int lrow = tid >> 3, lu = tid & 7;     // A fill coords
    const int bkr  = tid >> 4, bu = tid & 15;    // B fill coords

    auto fill = [&](int st, int kc) {
        const uint32_t sA = s0 + st * STG_BYTES;
        const uint32_t sB = sA + 16384;
        const int k0 = kc * 64;
        #pragma unroll
        for (int i = 0; i < 4; i++) {            // A: 128 rows x 8 x 16B
            int row = lrow + i * 32;
            uint32_t sw = ((lu ^ (row & 7)) << 4) + row * 128;
            const __half* srcA = wsrc + (size_t)row * NWw + k0 + lu * 8;
            asm volatile("cp.async.cg.shared.global [%0], [%1], 16;"
                         :: "r"(sA + sw), "l"(srcA));
        }
        #pragma unroll
        for (int i = 0; i < 4; i++) {            // B: 64 k-rows x 16 x 16B
            int kr = bkr + i * 16;
            uint32_t dst = sB + kr * 256 + ((bu ^ (kr & 7)) << 4);
            const __half* srcB =
                g_y2 + (size_t)(k0 + kr) * NPIX + p0 + bu * 8;
            asm volatile("cp.async.cg.shared.global [%0], [%1], 16;"
                         :: "r"(dst), "l"(srcB));
        }
        asm volatile("cp.async.commit_group;");
    };

    fill(0, 0);
    for (int kc = 0; kc < 8; kc++) {
        if (kc < 7) fill((kc + 1) & 1, kc + 1);
        if (kc < 7) asm volatile("cp.async.wait_group 1;");
        else        asm volatile("cp.async.wait_group 0;");
        __syncthreads();

        const uint32_t sA = s0 + (kc & 1) * STG_BYTES;
        const uint32_t sB = sA + 16384;

        #pragma unroll
        for (int ks = 0; ks < 4; ks++) {
            uint32_t a[4][4], bf[4][2];
            #pragma unroll
            for (int mi = 0; mi < 4; mi++) {
                int row = wm * 64 + mi * 16 + (lane & 15);
                uint32_t ad = sA + row * 128 + (((ks * 2 + (lane >> 4)) ^ (row & 7)) << 4);
                asm volatile(
                    "ldmatrix.sync.aligned.m8n8.x4.shared.b16 {%0,%1,%2,%3}, [%4];"
                    : "=r"(a[mi][0]), "=r"(a[mi][1]), "=r"(a[mi][2]), "=r"(a[mi][3])
                    : "r"(ad));
            }
            #pragma unroll
            for (int ni = 0; ni < 4; ni++) {
                int kr = ks * 16 + (lane & 15);
                uint32_t uu = wn * 4 + ni;
                uint32_t bd = sB + kr * 256 + ((uu ^ (kr & 7)) << 4);
                asm volatile(
                    "ldmatrix.sync.aligned.m8n8.x2.trans.shared.b16 {%0,%1}, [%2];"
                    : "=r"(bf[ni][0]), "=r"(bf[ni][1]) : "r"(bd));
            }
            #pragma unroll
            for (int mi = 0; mi < 4; mi++)
                #pragma unroll
                for (int ni = 0; ni < 4; ni++)
                    asm volatile(
                        "mma.sync.aligned.m16n8k16.row.col.f32.f16.f16.f32 "
                        "{%0,%1,%2,%3}, {%4,%5,%6,%7}, {%8,%9}, {%0,%1,%2,%3};"
                        : "+f"(acc[mi][ni][0]), "+f"(acc[mi][ni][1]),
                          "+f"(acc[mi][ni][2]), "+f"(acc[mi][ni][3])
                        : "r"(a[mi][0]), "r"(a[mi][1]), "r"(a[mi][2]), "r"(a[mi][3]),
                          "r"(bf[ni][0]), "r"(bf[ni][1]));
        }
        __syncthreads();
    }

    // epilogue: + b1[c] + x residual
    const int bb  = (int)(p0 >> 14);
    const int hw0 = (int)(p0 & 16383) + wn * 32 + (lane & 3) * 2;
    #pragma unroll
    for (int mi = 0; mi < 4; mi++) {
        int cb = mt * 128 + wm * 64 + mi * 16 + (lane >> 2);
        #pragma unroll
        for (int h = 0; h < 2; h++) {
            int c = cb + h * 8;
            float bias = __ldg(b1 + c);
            size_t base = ((size_t)(bb * Cc + c)) * HW + hw0;
            #pragma unroll
            for (int ni = 0; ni < 4; ni++) {
                size_t o = base + ni * 8;
                float2 xv = *(const float2*)(x + o);
                float2 r;
                r.x = acc[mi][ni][h * 2 + 0] + bias + xv.x;
                r.y = acc[mi][ni][h * 2 + 1] + bias + xv.y;
                *(float2*)(out + o) = r;
            }
        }
    }
}

// ---------------------------------------------------------------------------
extern "C" void kernel_launch(void* const* d_in, const int* in_sizes, int n_in,
                              void* d_out, int out_size) {
    const float* x     = (const float*)d_in[0];
    const float* gamma = (const float*)d_in[1];
    const float* beta  = (const float*)d_in[2];
    const float* lbp   = (const float*)d_in[3];
    const float* w1    = (const float*)d_in[4];
    const float* b1    = (const float*)d_in[5];
    float* out = (float*)d_out;

    static bool attr_done = false;
    if (!attr_done) {
        cudaFuncSetAttribute(gemm_kernel,
                             cudaFuncAttributeMaxDynamicSharedMemorySize,
                             2 * STG_BYTES);
        attr_done = true;
    }

    stats_part<<<dim3(Cc, Bn), 256>>>(x);
    finalize_stats<<<1, Cc>>>(gamma, beta);
    w1half<<<(Cc * NWw) / 1024, 256>>>(w1);
    dw_kernel<<<dim3(32, 16, Bn), 256>>>(x, lbp);
    gemm_kernel<<<dim3(2, NPIX / 128), 256, 2 * STG_BYTES>>>(x, b1, out);
}

// round 9
// speedup vs baseline: 1.9749x; 1.0127x over previous
#include <cuda_runtime.h>
#include <cuda_fp16.h>
#include <cstdint>

#define Cc   256
#define Bn   8
#define Hh   128
#define Ww   128
#define NWw  512
#define HW   (Hh*Ww)
#define NPIX (Bn*HW)
#define EPSf 1e-5f

typedef unsigned long long ull;

// ---- scratch ---------------------------------------------------------------
__device__ float  g_ps [Cc*Bn];
__device__ float  g_ps2[Cc*Bn];
__device__ float  g_scale[Cc];
__device__ float  g_shift[Cc];
__device__ __half g_w1h[Cc * NWw];               // [c][j]  A operand (K-major)
__device__ __half g_y2[(size_t)NWw * NPIX];      // [j][pixel]  B operand

__device__ __forceinline__ uint32_t smem_u32(const void* p) {
    uint32_t a;
    asm("{ .reg .u64 t; cvta.to.shared.u64 t, %1; cvt.u32.u64 %0, t; }"
        : "=r"(a) : "l"(p));
    return a;
}

#define PACK2(d, lo, hi) asm("mov.b64 %0, {%1, %2};" : "=l"(d) : "f"(lo), "f"(hi))
#define PACKB(d, v)      asm("mov.b64 %0, {%1, %1};" : "=l"(d) : "f"(v))
#define UNPACK2(lo, hi, s) asm("mov.b64 {%0, %1}, %2;" : "=f"(lo), "=f"(hi) : "l"(s))
#define MUL2(d, a, b)    asm("mul.rn.f32x2 %0, %1, %2;" : "=l"(d) : "l"(a), "l"(b))
#define FMA2(acc, a, b)  asm("fma.rn.f32x2 %0, %1, %2, %0;" : "+l"(acc) : "l"(a), "l"(b))

// ---------------------------------------------------------------------------
// Stats (2-stage, deterministic)
// ---------------------------------------------------------------------------
__global__ __launch_bounds__(256) void stats_part(const float* __restrict__ x) {
    int c = blockIdx.x, b = blockIdx.y, tid = threadIdx.x;
    const float4* p = (const float4*)(x + ((size_t)(b * Cc + c)) * HW);
    float s = 0.f, s2 = 0.f;
    #pragma unroll 4
    for (int i = tid; i < HW / 4; i += 256) {
        float4 v = __ldg(p + i);
        s  += v.x + v.y + v.z + v.w;
        s2 += v.x*v.x + v.y*v.y + v.z*v.z + v.w*v.w;
    }
    __shared__ float sh[256], sh2[256];
    sh[tid] = s; sh2[tid] = s2;
    __syncthreads();
    for (int off = 128; off > 0; off >>= 1) {
        if (tid < off) { sh[tid] += sh[tid+off]; sh2[tid] += sh2[tid+off]; }
        __syncthreads();
    }
    if (tid == 0) { g_ps[c*Bn + b] = sh[0]; g_ps2[c*Bn + b] = sh2[0]; }
}

__global__ void finalize_stats(const float* __restrict__ gamma,
                               const float* __restrict__ beta) {
    int c = threadIdx.x;
    float s = 0.f, s2 = 0.f;
    #pragma unroll
    for (int b = 0; b < Bn; b++) { s += g_ps[c*Bn+b]; s2 += g_ps2[c*Bn+b]; }
    float n = (float)(Bn * HW);
    float mean = s / n;
    float var  = s2 / n - mean * mean;
    float sc   = gamma[c] * rsqrtf(var + EPSf);
    g_scale[c] = sc;
    g_shift[c] = beta[c] - mean * sc;
}

__global__ void w1half(const float* __restrict__ w1) {
    int i = (blockIdx.x * 256 + threadIdx.x) * 4;
    float4 v = __ldg((const float4*)(w1 + i));
    __half2 a = __floats2half2_rn(v.x, v.y);
    __half2 b = __floats2half2_rn(v.z, v.w);
    uint2 o = make_uint2(*(uint32_t*)&a, *(uint32_t*)&b);
    *(uint2*)(g_w1h + i) = o;
}

// ---------------------------------------------------------------------------
// Kernel 2 (v6): BN -> depthwise 3x3 -> relu -> fp16 y2[j][pixel]
// Packed f32x2 stencil: the 2 j per input channel share x taps; weights
// packed {w0,w1}, x broadcast-packed -> 9 packed FMA per row instead of 18.
// ---------------------------------------------------------------------------
__global__ __launch_bounds__(256, 4)
void dw_kernel(const float* __restrict__ x, const float* __restrict__ lbp) {
    __shared__ float xs[8][10][136];           // 43520 B
    __shared__ float lw[16][9];

    const int tid   = threadIdx.x;
    const int chunk = blockIdx.x;              // 0..31
    const int h0    = blockIdx.y * 8;
    const int b     = blockIdx.z;
    const int cbase = chunk * 8;
    const int jbase = chunk * 16;

    if (tid < 80) {
        int ci = tid / 10, rr = tid - ci * 10;
        xs[ci][rr][3]   = 0.f;
        xs[ci][rr][132] = 0.f;
    }
    if (tid < 144) ((float*)lw)[tid] = __ldg(lbp + jbase * 9 + tid);

    #pragma unroll
    for (int ci = 0; ci < 8; ci++) {
        const float sc = g_scale[cbase + ci];
        const float sf = g_shift[cbase + ci];
        const float4* src =
            (const float4*)(x + ((size_t)(b * Cc + cbase + ci)) * HW);
        #pragma unroll
        for (int i = 0; i < 2; i++) {
            int idx = tid + i * 256;
            if (idx < 320) {
                int rr = idx >> 5, q = idx & 31;
                int hh = h0 - 1 + rr;
                float4 w = make_float4(0.f, 0.f, 0.f, 0.f);
                if ((unsigned)hh < (unsigned)Hh) {
                    float4 v = __ldg(src + hh * 32 + q);
                    w.x = fmaf(v.x, sc, sf);
                    w.y = fmaf(v.y, sc, sf);
                    w.z = fmaf(v.z, sc, sf);
                    w.w = fmaf(v.w, sc, sf);
                }
                *(float4*)&xs[ci][rr][4 + 4 * q] = w;
            }
        }
    }
    __syncthreads();

    const int p  = tid & 127;
    const int jh = tid >> 7;
    const size_t rowbase = (size_t)b * HW + (size_t)h0 * Ww + p;

    #pragma unroll
    for (int cidx = 0; cidx < 4; cidx++) {
        const int ci = jh * 4 + cidx;
        const int jl = ci * 2;
        ull pw[9];
        #pragma unroll
        for (int t = 0; t < 9; t++)
            PACK2(pw[t], lw[jl][t], lw[jl + 1][t]);

        const float* xr = &xs[ci][0][0];
        ull pa0, pa1, pa2, pb0, pb1, pb2;
        PACKB(pa0, xr[3 + p]);   PACKB(pa1, xr[4 + p]);   PACKB(pa2, xr[5 + p]);
        PACKB(pb0, xr[139 + p]); PACKB(pb1, xr[140 + p]); PACKB(pb2, xr[141 + p]);

        __half* y0p = g_y2 + (size_t)(jbase + jl) * NPIX + rowbase;
        __half* y1p = y0p + NPIX;
        #pragma unroll
        for (int r = 0; r < 8; r++) {
            const float* rc = xr + (r + 2) * 136 + p;
            ull pc0, pc1, pc2;
            PACKB(pc0, rc[3]); PACKB(pc1, rc[4]); PACKB(pc2, rc[5]);
            ull acc;
            MUL2(acc, pw[0], pa0);
            FMA2(acc, pw[1], pa1);
            FMA2(acc, pw[2], pa2);
            FMA2(acc, pw[3], pb0);
            FMA2(acc, pw[4], pb1);
            FMA2(acc, pw[5], pb2);
            FMA2(acc, pw[6], pc0);
            FMA2(acc, pw[7], pc1);
            FMA2(acc, pw[8], pc2);
            float s0, s1;
            UNPACK2(s0, s1, acc);
            y0p[r * Ww] = __float2half_rn(fmaxf(s0, 0.f));
            y1p[r * Ww] = __float2half_rn(fmaxf(s1, 0.f));
            pa0 = pb0; pa1 = pb1; pa2 = pb2;
            pb0 = pc0; pb1 = pc1; pb2 = pc2;
        }
    }
}

// ---------------------------------------------------------------------------
// Kernel 3: HMMA GEMM (unchanged — at HMMA floor), B from y2[j][pixel]
// ---------------------------------------------------------------------------
#define STG_BYTES 32768   // per stage: A 16KB + B 16KB

__global__ __launch_bounds__(256)
void gemm_kernel(const float* __restrict__ x, const float* __restrict__ b1,
                 float* __restrict__ out) {
    extern __shared__ __align__(1024) char dsm[];
    const uint32_t s0 = smem_u32(dsm);

    const int tid  = threadIdx.x;
    const int wid  = tid >> 5, lane = tid & 31;
    const int wm   = wid & 1;
    const int wn   = wid >> 1;
    const int mt   = blockIdx.x;
    const size_t p0 = (size_t)blockIdx.y * 128;

    float acc[4][4][4];
    #pragma unroll
    for (int mi = 0; mi < 4; mi++)
        #pragma unroll
        for (int ni = 0; ni < 4; ni++)
            #pragma unroll
            for (int q = 0; q < 4; q++) acc[mi][ni][q] = 0.f;

    const __half* wsrc = g_w1h + (size_t)mt * 128 * NWw;
    const int lrow = tid >> 3, lu = tid & 7;     // A fill coords
    const int bkr  = tid >> 4, bu = tid & 15;    // B fill coords

    auto fill = [&](int st, int kc) {
        const uint32_t sA = s0 + st * STG_BYTES;
        const uint32_t sB = sA + 16384;
        const int k0 = kc * 64;
        #pragma unroll
        for (int i = 0; i < 4; i++) {            // A: 128 rows x 8 x 16B
            int row = lrow + i * 32;
            uint32_t sw = ((lu ^ (row & 7)) << 4) + row * 128;
            const __half* srcA = wsrc + (size_t)row * NWw + k0 + lu * 8;
            asm volatile("cp.async.cg.shared.global [%0], [%1], 16;"
                         :: "r"(sA + sw), "l"(srcA));
        }
        #pragma unroll
        for (int i = 0; i < 4; i++) {            // B: 64 k-rows x 16 x 16B
            int kr = bkr + i * 16;
            uint32_t dst = sB + kr * 256 + ((bu ^ (kr & 7)) << 4);
            const __half* srcB =
                g_y2 + (size_t)(k0 + kr) * NPIX + p0 + bu * 8;
            asm volatile("cp.async.cg.shared.global [%0], [%1], 16;"
                         :: "r"(dst), "l"(srcB));
        }
        asm volatile("cp.async.commit_group;");
    };

    fill(0, 0);
    for (int kc = 0; kc < 8; kc++) {
        if (kc < 7) fill((kc + 1) & 1, kc + 1);
        if (kc < 7) asm volatile("cp.async.wait_group 1;");
        else        asm volatile("cp.async.wait_group 0;");
        __syncthreads();

        const uint32_t sA = s0 + (kc & 1) * STG_BYTES;
        const uint32_t sB = sA + 16384;

        #pragma unroll
        for (int ks = 0; ks < 4; ks++) {
            uint32_t a[4][4], bf[4][2];
            #pragma unroll
            for (int mi = 0; mi < 4; mi++) {
                int row = wm * 64 + mi * 16 + (lane & 15);
                uint32_t ad = sA + row * 128 + (((ks * 2 + (lane >> 4)) ^ (row & 7)) << 4);
                asm volatile(
                    "ldmatrix.sync.aligned.m8n8.x4.shared.b16 {%0,%1,%2,%3}, [%4];"
                    : "=r"(a[mi][0]), "=r"(a[mi][1]), "=r"(a[mi][2]), "=r"(a[mi][3])
                    : "r"(ad));
            }
            #pragma unroll
            for (int ni = 0; ni < 4; ni++) {
                int kr = ks * 16 + (lane & 15);
                uint32_t uu = wn * 4 + ni;
                uint32_t bd = sB + kr * 256 + ((uu ^ (kr & 7)) << 4);
                asm volatile(
                    "ldmatrix.sync.aligned.m8n8.x2.trans.shared.b16 {%0,%1}, [%2];"
                    : "=r"(bf[ni][0]), "=r"(bf[ni][1]) : "r"(bd));
            }
            #pragma unroll
            for (int mi = 0; mi < 4; mi++)
                #pragma unroll
                for (int ni = 0; ni < 4; ni++)
                    asm volatile(
                        "mma.sync.aligned.m16n8k16.row.col.f32.f16.f16.f32 "
                        "{%0,%1,%2,%3}, {%4,%5,%6,%7}, {%8,%9}, {%0,%1,%2,%3};"
                        : "+f"(acc[mi][ni][0]), "+f"(acc[mi][ni][1]),
                          "+f"(acc[mi][ni][2]), "+f"(acc[mi][ni][3])
                        : "r"(a[mi][0]), "r"(a[mi][1]), "r"(a[mi][2]), "r"(a[mi][3]),
                          "r"(bf[ni][0]), "r"(bf[ni][1]));
        }
        __syncthreads();
    }

    // epilogue: + b1[c] + x residual
    const int bb  = (int)(p0 >> 14);
    const int hw0 = (int)(p0 & 16383) + wn * 32 + (lane & 3) * 2;
    #pragma unroll
    for (int mi = 0; mi < 4; mi++) {
        int cb = mt * 128 + wm * 64 + mi * 16 + (lane >> 2);
        #pragma unroll
        for (int h = 0; h < 2; h++) {
            int c = cb + h * 8;
            float bias = __ldg(b1 + c);
            size_t base = ((size_t)(bb * Cc + c)) * HW + hw0;
            #pragma unroll
            for (int ni = 0; ni < 4; ni++) {
                size_t o = base + ni * 8;
                float2 xv = *(const float2*)(x + o);
                float2 r;
                r.x = acc[mi][ni][h * 2 + 0] + bias + xv.x;
                r.y = acc[mi][ni][h * 2 + 1] + bias + xv.y;
                *(float2*)(out + o) = r;
            }
        }
    }
}

// ---------------------------------------------------------------------------
extern "C" void kernel_launch(void* const* d_in, const int* in_sizes, int n_in,
                              void* d_out, int out_size) {
    const float* x     = (const float*)d_in[0];
    const float* gamma = (const float*)d_in[1];
    const float* beta  = (const float*)d_in[2];
    const float* lbp   = (const float*)d_in[3];
    const float* w1    = (const float*)d_in[4];
    const float* b1    = (const float*)d_in[5];
    float* out = (float*)d_out;

    static bool attr_done = false;
    if (!attr_done) {
        cudaFuncSetAttribute(gemm_kernel,
                             cudaFuncAttributeMaxDynamicSharedMemorySize,
                             2 * STG_BYTES);
        attr_done = true;
    }

    stats_part<<<dim3(Cc, Bn), 256>>>(x);
    finalize_stats<<<1, Cc>>>(gamma, beta);
    w1half<<<(Cc * NWw) / 1024, 256>>>(w1);
    dw_kernel<<<dim3(32, 16, Bn), 256>>>(x, lbp);
    gemm_kernel<<<dim3(2, NPIX / 128), 256, 2 * STG_BYTES>>>(x, b1, out);
}

// round 10
// speedup vs baseline: 2.0358x; 1.0309x over previous
#include <cuda_runtime.h>
#include <cuda_fp16.h>
#include <cstdint>

#define Cc   256
#define Bn   8
#define Hh   128
#define Ww   128
#define NWw  512
#define HW   (Hh*Ww)
#define NPIX (Bn*HW)
#define EPSf 1e-5f

typedef unsigned long long ull;

// ---- scratch ---------------------------------------------------------------
__device__ float  g_ps [Cc*Bn];
__device__ float  g_ps2[Cc*Bn];
__device__ float  g_scale[Cc];
__device__ float  g_shift[Cc];
__device__ __half g_w1h[Cc * NWw];               // [c][j]  A operand (K-major)
__device__ __half g_y2[(size_t)NWw * NPIX];      // [j][pixel]  B operand

__device__ __forceinline__ uint32_t smem_u32(const void* p) {
    uint32_t a;
    asm("{ .reg .u64 t; cvta.to.shared.u64 t, %1; cvt.u32.u64 %0, t; }"
        : "=r"(a) : "l"(p));
    return a;
}

#define PACK2(d, lo, hi) asm("mov.b64 %0, {%1, %2};" : "=l"(d) : "f"(lo), "f"(hi))
#define PACKB(d, v)      asm("mov.b64 %0, {%1, %1};" : "=l"(d) : "f"(v))
#define UNPACK2(lo, hi, s) asm("mov.b64 {%0, %1}, %2;" : "=f"(lo), "=f"(hi) : "l"(s))
#define MUL2(d, a, b)    asm("mul.rn.f32x2 %0, %1, %2;" : "=l"(d) : "l"(a), "l"(b))
#define FMA2(acc, a, b)  asm("fma.rn.f32x2 %0, %1, %2, %0;" : "+l"(acc) : "l"(a), "l"(b))

// ---------------------------------------------------------------------------
// Stats (2-stage, deterministic)
// ---------------------------------------------------------------------------
__global__ __launch_bounds__(256) void stats_part(const float* __restrict__ x) {
    int c = blockIdx.x, b = blockIdx.y, tid = threadIdx.x;
    const float4* p = (const float4*)(x + ((size_t)(b * Cc + c)) * HW);
    float s = 0.f, s2 = 0.f;
    #pragma unroll 4
    for (int i = tid; i < HW / 4; i += 256) {
        float4 v = __ldg(p + i);
        s  += v.x + v.y + v.z + v.w;
        s2 += v.x*v.x + v.y*v.y + v.z*v.z + v.w*v.w;
    }
    __shared__ float sh[256], sh2[256];
    sh[tid] = s; sh2[tid] = s2;
    __syncthreads();
    for (int off = 128; off > 0; off >>= 1) {
        if (tid < off) { sh[tid] += sh[tid+off]; sh2[tid] += sh2[tid+off]; }
        __syncthreads();
    }
    if (tid == 0) { g_ps[c*Bn + b] = sh[0]; g_ps2[c*Bn + b] = sh2[0]; }
}

__global__ void finalize_stats(const float* __restrict__ gamma,
                               const float* __restrict__ beta) {
    int c = threadIdx.x;
    float s = 0.f, s2 = 0.f;
    #pragma unroll
    for (int b = 0; b < Bn; b++) { s += g_ps[c*Bn+b]; s2 += g_ps2[c*Bn+b]; }
    float n = (float)(Bn * HW);
    float mean = s / n;
    float var  = s2 / n - mean * mean;
    float sc   = gamma[c] * rsqrtf(var + EPSf);
    g_scale[c] = sc;
    g_shift[c] = beta[c] - mean * sc;
}

__global__ void w1half(const float* __restrict__ w1) {
    int i = (blockIdx.x * 256 + threadIdx.x) * 4;
    float4 v = __ldg((const float4*)(w1 + i));
    __half2 a = __floats2half2_rn(v.x, v.y);
    __half2 b = __floats2half2_rn(v.z, v.w);
    uint2 o = make_uint2(*(uint32_t*)&a, *(uint32_t*)&b);
    *(uint2*)(g_w1h + i) = o;
}

// ---------------------------------------------------------------------------
// Kernel 2 (v7): BN -> depthwise 3x3 -> relu -> fp16 y2[j][pixel]
// f32x2 with TWO ADJACENT PIXELS in the lanes; weights broadcast-packed once
// per cidx. Per row: 3 LDS.64 + 3 packs + 18 FMA2 -> 4 outputs (2px x 2j).
// ---------------------------------------------------------------------------
__global__ __launch_bounds__(256, 3)
void dw_kernel(const float* __restrict__ x, const float* __restrict__ lbp) {
    __shared__ float xs[8][10][136];           // 43520 B
    __shared__ float lw[16][9];

    const int tid   = threadIdx.x;
    const int chunk = blockIdx.x;              // 0..31
    const int h0    = blockIdx.y * 8;
    const int b     = blockIdx.z;
    const int cbase = chunk * 8;
    const int jbase = chunk * 16;

    if (tid < 80) {
        int ci = tid / 10, rr = tid - ci * 10;
        xs[ci][rr][3]   = 0.f;
        xs[ci][rr][132] = 0.f;
    }
    if (tid < 144) ((float*)lw)[tid] = __ldg(lbp + jbase * 9 + tid);

    #pragma unroll
    for (int ci = 0; ci < 8; ci++) {
        const float sc = g_scale[cbase + ci];
        const float sf = g_shift[cbase + ci];
        const float4* src =
            (const float4*)(x + ((size_t)(b * Cc + cbase + ci)) * HW);
        #pragma unroll
        for (int i = 0; i < 2; i++) {
            int idx = tid + i * 256;
            if (idx < 320) {
                int rr = idx >> 5, q = idx & 31;
                int hh = h0 - 1 + rr;
                float4 w = make_float4(0.f, 0.f, 0.f, 0.f);
                if ((unsigned)hh < (unsigned)Hh) {
                    float4 v = __ldg(src + hh * 32 + q);
                    w.x = fmaf(v.x, sc, sf);
                    w.y = fmaf(v.y, sc, sf);
                    w.z = fmaf(v.z, sc, sf);
                    w.w = fmaf(v.w, sc, sf);
                }
                *(float4*)&xs[ci][rr][4 + 4 * q] = w;
            }
        }
    }
    __syncthreads();

    const int pp  = tid & 63;                  // pixel pair 0..63
    const int grp = tid >> 6;                  // 0..3
    const int px  = pp * 2;
    const size_t rowbase = (size_t)b * HW + (size_t)h0 * Ww + px;

    #pragma unroll
    for (int cidx = 0; cidx < 2; cidx++) {
        const int ci = grp * 2 + cidx;
        const int jl = ci * 2;
        ull pw0[9], pw1[9];
        #pragma unroll
        for (int t = 0; t < 9; t++) {
            PACKB(pw0[t], lw[jl][t]);
            PACKB(pw1[t], lw[jl + 1][t]);
        }

        const float* xr = &xs[ci][0][0];
        const int e = 2 + px;                  // even smem index (8B aligned)

        ull Ta0, Ta1, Ta2, Tb0, Tb1, Tb2;
        {
            float2 lm = *(const float2*)&xr[e];
            float2 l0 = *(const float2*)&xr[e + 2];
            float2 lp = *(const float2*)&xr[e + 4];
            PACK2(Ta0, lm.y, l0.x);
            PACK2(Ta1, l0.x, l0.y);
            PACK2(Ta2, l0.y, lp.x);
            lm = *(const float2*)&xr[136 + e];
            l0 = *(const float2*)&xr[136 + e + 2];
            lp = *(const float2*)&xr[136 + e + 4];
            PACK2(Tb0, lm.y, l0.x);
            PACK2(Tb1, l0.x, l0.y);
            PACK2(Tb2, l0.y, lp.x);
        }

        __half2* y0p = (__half2*)(g_y2 + (size_t)(jbase + jl) * NPIX + rowbase);
        __half2* y1p = (__half2*)((__half*)y0p + NPIX);

        #pragma unroll
        for (int r = 0; r < 8; r++) {
            const float* rc = xr + (r + 2) * 136 + e;
            float2 lm = *(const float2*)rc;
            float2 l0 = *(const float2*)(rc + 2);
            float2 lp = *(const float2*)(rc + 4);
            ull Tc0, Tc1, Tc2;
            PACK2(Tc0, lm.y, l0.x);
            PACK2(Tc1, l0.x, l0.y);
            PACK2(Tc2, l0.y, lp.x);

            ull a0, a1;
            MUL2(a0, pw0[0], Ta0);          MUL2(a1, pw1[0], Ta0);
            FMA2(a0, pw0[1], Ta1);          FMA2(a1, pw1[1], Ta1);
            FMA2(a0, pw0[2], Ta2);          FMA2(a1, pw1[2], Ta2);
            FMA2(a0, pw0[3], Tb0);          FMA2(a1, pw1[3], Tb0);
            FMA2(a0, pw0[4], Tb1);          FMA2(a1, pw1[4], Tb1);
            FMA2(a0, pw0[5], Tb2);          FMA2(a1, pw1[5], Tb2);
            FMA2(a0, pw0[6], Tc0);          FMA2(a1, pw1[6], Tc0);
            FMA2(a0, pw0[7], Tc1);          FMA2(a1, pw1[7], Tc1);
            FMA2(a0, pw0[8], Tc2);          FMA2(a1, pw1[8], Tc2);

            float s0l, s0h, s1l, s1h;
            UNPACK2(s0l, s0h, a0);
            UNPACK2(s1l, s1h, a1);
            y0p[r * (Ww / 2)] =
                __floats2half2_rn(fmaxf(s0l, 0.f), fmaxf(s0h, 0.f));
            y1p[r * (Ww / 2)] =
                __floats2half2_rn(fmaxf(s1l, 0.f), fmaxf(s1h, 0.f));

            Ta0 = Tb0; Ta1 = Tb1; Ta2 = Tb2;
            Tb0 = Tc0; Tb1 = Tc1; Tb2 = Tc2;
        }
    }
}

// ---------------------------------------------------------------------------
// Kernel 3: HMMA GEMM (unchanged — at HMMA floor), B from y2[j][pixel]
// ---------------------------------------------------------------------------
#define STG_BYTES 32768   // per stage: A 16KB + B 16KB

__global__ __launch_bounds__(256)
void gemm_kernel(const float* __restrict__ x, const float* __restrict__ b1,
                 float* __restrict__ out) {
    extern __shared__ __align__(1024) char dsm[];
    const uint32_t s0 = smem_u32(dsm);

    const int tid  = threadIdx.x;
    const int wid  = tid >> 5, lane = tid & 31;
    const int wm   = wid & 1;
    const int wn   = wid >> 1;
    const int mt   = blockIdx.x;
    const size_t p0 = (size_t)blockIdx.y * 128;

    float acc[4][4][4];
    #pragma unroll
    for (int mi = 0; mi < 4; mi++)
        #pragma unroll
        for (int ni = 0; ni < 4; ni++)
            #pragma unroll
            for (int q = 0; q < 4; q++) acc[mi][ni][q] = 0.f;

    const __half* wsrc = g_w1h + (size_t)mt * 128 * NWw;
    const int lrow = tid >> 3, lu = tid & 7;     // A fill coords
    const int bkr  = tid >> 4, bu = tid & 15;    // B fill coords

    auto fill = [&](int st, int kc) {
        const uint32_t sA = s0 + st * STG_BYTES;
        const uint32_t sB = sA + 16384;
        const int k0 = kc * 64;
        #pragma unroll
        for (int i = 0; i < 4; i++) {            // A: 128 rows x 8 x 16B
            int row = lrow + i * 32;
            uint32_t sw = ((lu ^ (row & 7)) << 4) + row * 128;
            const __half* srcA = wsrc + (size_t)row * NWw + k0 + lu * 8;
            asm volatile("cp.async.cg.shared.global [%0], [%1], 16;"
                         :: "r"(sA + sw), "l"(srcA));
        }
        #pragma unroll
        for (int i = 0; i < 4; i++) {            // B: 64 k-rows x 16 x 16B
            int kr = bkr + i * 16;
            uint32_t dst = sB + kr * 256 + ((bu ^ (kr & 7)) << 4);
            const __half* srcB =
                g_y2 + (size_t)(k0 + kr) * NPIX + p0 + bu * 8;
            asm volatile("cp.async.cg.shared.global [%0], [%1], 16;"
                         :: "r"(dst), "l"(srcB));
        }
        asm volatile("cp.async.commit_group;");
    };

    fill(0, 0);
    for (int kc = 0; kc < 8; kc++) {
        if (kc < 7) fill((kc + 1) & 1, kc + 1);
        if (kc < 7) asm volatile("cp.async.wait_group 1;");
        else        asm volatile("cp.async.wait_group 0;");
        __syncthreads();

        const uint32_t sA = s0 + (kc & 1) * STG_BYTES;
        const uint32_t sB = sA + 16384;

        #pragma unroll
        for (int ks = 0; ks < 4; ks++) {
            uint32_t a[4][4], bf[4][2];
            #pragma unroll
            for (int mi = 0; mi < 4; mi++) {
                int row = wm * 64 + mi * 16 + (lane & 15);
                uint32_t ad = sA + row * 128 + (((ks * 2 + (lane >> 4)) ^ (row & 7)) << 4);
                asm volatile(
                    "ldmatrix.sync.aligned.m8n8.x4.shared.b16 {%0,%1,%2,%3}, [%4];"
                    : "=r"(a[mi][0]), "=r"(a[mi][1]), "=r"(a[mi][2]), "=r"(a[mi][3])
                    : "r"(ad));
            }
            #pragma unroll
            for (int ni = 0; ni < 4; ni++) {
                int kr = ks * 16 + (lane & 15);
                uint32_t uu = wn * 4 + ni;
                uint32_t bd = sB + kr * 256 + ((uu ^ (kr & 7)) << 4);
                asm volatile(
                    "ldmatrix.sync.aligned.m8n8.x2.trans.shared.b16 {%0,%1}, [%2];"
                    : "=r"(bf[ni][0]), "=r"(bf[ni][1]) : "r"(bd));
            }
            #pragma unroll
            for (int mi = 0; mi < 4; mi++)
                #pragma unroll
                for (int ni = 0; ni < 4; ni++)
                    asm volatile(
                        "mma.sync.aligned.m16n8k16.row.col.f32.f16.f16.f32 "
                        "{%0,%1,%2,%3}, {%4,%5,%6,%7}, {%8,%9}, {%0,%1,%2,%3};"
                        : "+f"(acc[mi][ni][0]), "+f"(acc[mi][ni][1]),
                          "+f"(acc[mi][ni][2]), "+f"(acc[mi][ni][3])
                        : "r"(a[mi][0]), "r"(a[mi][1]), "r"(a[mi][2]), "r"(a[mi][3]),
                          "r"(bf[ni][0]), "r"(bf[ni][1]));
        }
        __syncthreads();
    }

    // epilogue: + b1[c] + x residual
    const int bb  = (int)(p0 >> 14);
    const int hw0 = (int)(p0 & 16383) + wn * 32 + (lane & 3) * 2;
    #pragma unroll
    for (int mi = 0; mi < 4; mi++) {
        int cb = mt * 128 + wm * 64 + mi * 16 + (lane >> 2);
        #pragma unroll
        for (int h = 0; h < 2; h++) {
            int c = cb + h * 8;
            float bias = __ldg(b1 + c);
            size_t base = ((size_t)(bb * Cc + c)) * HW + hw0;
            #pragma unroll
            for (int ni = 0; ni < 4; ni++) {
                size_t o = base + ni * 8;
                float2 xv = *(const float2*)(x + o);
                float2 r;
                r.x = acc[mi][ni][h * 2 + 0] + bias + xv.x;
                r.y = acc[mi][ni][h * 2 + 1] + bias + xv.y;
                *(float2*)(out + o) = r;
            }
        }
    }
}

// ---------------------------------------------------------------------------
extern "C" void kernel_launch(void* const* d_in, const int* in_sizes, int n_in,
                              void* d_out, int out_size) {
    const float* x     = (const float*)d_in[0];
    const float* gamma = (const float*)d_in[1];
    const float* beta  = (const float*)d_in[2];
    const float* lbp   = (const float*)d_in[3];
    const float* w1    = (const float*)d_in[4];
    const float* b1    = (const float*)d_in[5];
    float* out = (float*)d_out;

    static bool attr_done = false;
    if (!attr_done) {
        cudaFuncSetAttribute(gemm_kernel,
                             cudaFuncAttributeMaxDynamicSharedMemorySize,
                             2 * STG_BYTES);
        attr_done = true;
    }

    stats_part<<<dim3(Cc, Bn), 256>>>(x);
    finalize_stats<<<1, Cc>>>(gamma, beta);
    w1half<<<(Cc * NWw) / 1024, 256>>>(w1);
    dw_kernel<<<dim3(32, 16, Bn), 256>>>(x, lbp);
    gemm_kernel<<<dim3(2, NPIX / 128), 256, 2 * STG_BYTES>>>(x, b1, out);
}

// round 11
// speedup vs baseline: 2.1284x; 1.0455x over previous
#include <cuda_runtime.h>
#include <cuda_fp16.h>
#include <cstdint>

#define Cc   256
#define Bn   8
#define Hh   128
#define Ww   128
#define NWw  512
#define HW   (Hh*Ww)
#define NPIX (Bn*HW)
#define EPSf 1e-5f

typedef unsigned long long ull;

// ---- scratch ---------------------------------------------------------------
__device__ float  g_ps [Cc*Bn];
__device__ float  g_ps2[Cc*Bn];
__device__ float  g_scale[Cc];
__device__ float  g_shift[Cc];
__device__ __half g_w1h[Cc * NWw];               // [c][j]  A operand (K-major)
__device__ __half g_y2[(size_t)NWw * NPIX];      // [j][pixel]  B operand

__device__ __forceinline__ uint32_t smem_u32(const void* p) {
    uint32_t a;
    asm("{ .reg .u64 t; cvta.to.shared.u64 t, %1; cvt.u32.u64 %0, t; }"
        : "=r"(a) : "l"(p));
    return a;
}

#define PACK2(d, lo, hi) asm("mov.b64 %0, {%1, %2};" : "=l"(d) : "f"(lo), "f"(hi))
#define PACKB(d, v)      asm("mov.b64 %0, {%1, %1};" : "=l"(d) : "f"(v))
#define UNPACK2(lo, hi, s) asm("mov.b64 {%0, %1}, %2;" : "=f"(lo), "=f"(hi) : "l"(s))
#define MUL2(d, a, b)    asm("mul.rn.f32x2 %0, %1, %2;" : "=l"(d) : "l"(a), "l"(b))
#define FMA2(acc, a, b)  asm("fma.rn.f32x2 %0, %1, %2, %0;" : "+l"(acc) : "l"(a), "l"(b))

// ---------------------------------------------------------------------------
// Stats (2-stage, deterministic)
// ---------------------------------------------------------------------------
__global__ __launch_bounds__(256) void stats_part(const float* __restrict__ x) {
    int c = blockIdx.x, b = blockIdx.y, tid = threadIdx.x;
    const float4* p = (const float4*)(x + ((size_t)(b * Cc + c)) * HW);
    float s = 0.f, s2 = 0.f;
    #pragma unroll 4
    for (int i = tid; i < HW / 4; i += 256) {
        float4 v = __ldg(p + i);
        s  += v.x + v.y + v.z + v.w;
        s2 += v.x*v.x + v.y*v.y + v.z*v.z + v.w*v.w;
    }
    __shared__ float sh[256], sh2[256];
    sh[tid] = s; sh2[tid] = s2;
    __syncthreads();
    for (int off = 128; off > 0; off >>= 1) {
        if (tid < off) { sh[tid] += sh[tid+off]; sh2[tid] += sh2[tid+off]; }
        __syncthreads();
    }
    if (tid == 0) { g_ps[c*Bn + b] = sh[0]; g_ps2[c*Bn + b] = sh2[0]; }
}

__global__ void finalize_stats(const float* __restrict__ gamma,
                               const float* __restrict__ beta) {
    int c = threadIdx.x;
    float s = 0.f, s2 = 0.f;
    #pragma unroll
    for (int b = 0; b < Bn; b++) { s += g_ps[c*Bn+b]; s2 += g_ps2[c*Bn+b]; }
    float n = (float)(Bn * HW);
    float mean = s / n;
    float var  = s2 / n - mean * mean;
    float sc   = gamma[c] * rsqrtf(var + EPSf);
    g_scale[c] = sc;
    g_shift[c] = beta[c] - mean * sc;
}

__global__ void w1half(const float* __restrict__ w1) {
    int i = (blockIdx.x * 256 + threadIdx.x) * 4;
    float4 v = __ldg((const float4*)(w1 + i));
    __half2 a = __floats2half2_rn(v.x, v.y);
    __half2 b = __floats2half2_rn(v.z, v.w);
    uint2 o = make_uint2(*(uint32_t*)&a, *(uint32_t*)&b);
    *(uint2*)(g_w1h + i) = o;
}

// ---------------------------------------------------------------------------
// Kernel 2 (v8): BN -> depthwise 3x3 -> relu -> fp16 y2[j][pixel]
// Block: 4 input channels (8 j) x 16-row strip x 128 cols, 256 threads,
// 1 (ci, 2j, 2px) workload per thread. Weights packed once/thread.
// Per row: 1 LDS.64 + 2 LDS.32 + 2 packs + 18 FMA2 -> 4 outputs.
// ---------------------------------------------------------------------------
__global__ __launch_bounds__(256, 3)
void dw_kernel(const float* __restrict__ x, const float* __restrict__ lbp) {
    __shared__ float xs[4][18][136];           // 39168 B
    __shared__ float lw[8][9];

    const int tid   = threadIdx.x;
    const int chunk = blockIdx.x;              // 0..63 (4-ch chunks)
    const int h0    = blockIdx.y * 16;         // 16-row strip
    const int b     = blockIdx.z;
    const int cbase = chunk * 4;
    const int jbase = chunk * 8;

    // pad columns [3],[132] per (ci,row): 4*18*2 = 144 writes
    if (tid < 144) {
        int ci = tid / 36, r2 = tid - ci * 36;
        int rr = r2 >> 1, side = r2 & 1;
        xs[ci][rr][side ? 132 : 3] = 0.f;
    }
    if (tid < 72) ((float*)lw)[tid] = __ldg(lbp + jbase * 9 + tid);

    // main tile: 4 ch x 18 rows x 32 float4 = 2304 float4, exactly 9 iters
    #pragma unroll
    for (int i = 0; i < 9; i++) {
        int idx = tid + i * 256;
        int ci  = idx / 576;
        int rem = idx - ci * 576;
        int rr  = rem >> 5, q = rem & 31;
        int hh  = h0 - 1 + rr;
        float4 w = make_float4(0.f, 0.f, 0.f, 0.f);
        if ((unsigned)hh < (unsigned)Hh) {
            float sc = g_scale[cbase + ci];
            float sf = g_shift[cbase + ci];
            float4 v = __ldg((const float4*)(x + ((size_t)(b * Cc + cbase + ci)) * HW)
                             + hh * 32 + q);
            w.x = fmaf(v.x, sc, sf);
            w.y = fmaf(v.y, sc, sf);
            w.z = fmaf(v.z, sc, sf);
            w.w = fmaf(v.w, sc, sf);
        }
        *(float4*)&xs[ci][rr][4 + 4 * q] = w;
    }
    __syncthreads();

    const int pp = tid & 63;                   // pixel pair 0..63
    const int ci = tid >> 6;                   // 0..3
    const int jl = ci * 2;
    const int px = pp * 2;

    ull pw0[9], pw1[9];
    #pragma unroll
    for (int t = 0; t < 9; t++) {
        PACKB(pw0[t], lw[jl][t]);
        PACKB(pw1[t], lw[jl + 1][t]);
    }

    const float* xr = &xs[ci][0][0];
    const int e = 4 + px;                      // even smem index (8B aligned)

    // load shifted-pair triple for a row: P0=(px-1,px) P1=(px,px+1) P2=(px+1,px+2)
    ull Ta0, Ta1, Ta2, Tb0, Tb1, Tb2;
    {
        float m1 = xr[e - 1];
        Ta1 = *(const ull*)&xr[e];
        float p2 = xr[e + 2];
        float mlo, mhi; UNPACK2(mlo, mhi, Ta1);
        PACK2(Ta0, m1, mlo);
        PACK2(Ta2, mhi, p2);
        m1  = xr[136 + e - 1];
        Tb1 = *(const ull*)&xr[136 + e];
        p2  = xr[136 + e + 2];
        UNPACK2(mlo, mhi, Tb1);
        PACK2(Tb0, m1, mlo);
        PACK2(Tb2, mhi, p2);
    }

    const __half2 zero2 = __floats2half2_rn(0.f, 0.f);
    __half2* y0p = (__half2*)(g_y2 + (size_t)(jbase + jl) * NPIX
                              + (size_t)b * HW + (size_t)h0 * Ww + px);
    __half2* y1p = (__half2*)((__half*)y0p + NPIX);

    #pragma unroll
    for (int r = 0; r < 16; r++) {
        const float* rc = xr + (r + 2) * 136 + e;
        float m1 = rc[-1];
        ull Tc1 = *(const ull*)rc;
        float p2 = rc[2];
        float mlo, mhi; UNPACK2(mlo, mhi, Tc1);
        ull Tc0, Tc2;
        PACK2(Tc0, m1, mlo);
        PACK2(Tc2, mhi, p2);

        ull a0, a1;
        MUL2(a0, pw0[0], Ta0);          MUL2(a1, pw1[0], Ta0);
        FMA2(a0, pw0[1], Ta1);          FMA2(a1, pw1[1], Ta1);
        FMA2(a0, pw0[2], Ta2);          FMA2(a1, pw1[2], Ta2);
        FMA2(a0, pw0[3], Tb0);          FMA2(a1, pw1[3], Tb0);
        FMA2(a0, pw0[4], Tb1);          FMA2(a1, pw1[4], Tb1);
        FMA2(a0, pw0[5], Tb2);          FMA2(a1, pw1[5], Tb2);
        FMA2(a0, pw0[6], Tc0);          FMA2(a1, pw1[6], Tc0);
        FMA2(a0, pw0[7], Tc1);          FMA2(a1, pw1[7], Tc1);
        FMA2(a0, pw0[8], Tc2);          FMA2(a1, pw1[8], Tc2);

        float s0l, s0h, s1l, s1h;
        UNPACK2(s0l, s0h, a0);
        UNPACK2(s1l, s1h, a1);
        y0p[r * 64] = __hmax2(__floats2half2_rn(s0l, s0h), zero2);
        y1p[r * 64] = __hmax2(__floats2half2_rn(s1l, s1h), zero2);

        Ta0 = Tb0; Ta1 = Tb1; Ta2 = Tb2;
        Tb0 = Tc0; Tb1 = Tc1; Tb2 = Tc2;
    }
}

// ---------------------------------------------------------------------------
// Kernel 3: HMMA GEMM (unchanged — at HMMA floor), B from y2[j][pixel]
// ---------------------------------------------------------------------------
#define STG_BYTES 32768   // per stage: A 16KB + B 16KB

__global__ __launch_bounds__(256)
void gemm_kernel(const float* __restrict__ x, const float* __restrict__ b1,
                 float* __restrict__ out) {
    extern __shared__ __align__(1024) char dsm[];
    const uint32_t s0 = smem_u32(dsm);

    const int tid  = threadIdx.x;
    const int wid  = tid >> 5, lane = tid & 31;
    const int wm   = wid & 1;
    const int wn   = wid >> 1;
    const int mt   = blockIdx.x;
    const size_t p0 = (size_t)blockIdx.y * 128;

    float acc[4][4][4];
    #pragma unroll
    for (int mi = 0; mi < 4; mi++)
        #pragma unroll
        for (int ni = 0; ni < 4; ni++)
            #pragma unroll
            for (int q = 0; q < 4; q++) acc[mi][ni][q] = 0.f;

    const __half* wsrc = g_w1h + (size_t)mt * 128 * NWw;
    const int lrow = tid >> 3, lu = tid & 7;     // A fill coords
    const int bkr  = tid >> 4, bu = tid & 15;    // B fill coords

    auto fill = [&](int st, int kc) {
        const uint32_t sA = s0 + st * STG_BYTES;
        const uint32_t sB = sA + 16384;
        const int k0 = kc * 64;
        #pragma unroll
        for (int i = 0; i < 4; i++) {            // A: 128 rows x 8 x 16B
            int row = lrow + i * 32;
            uint32_t sw = ((lu ^ (row & 7)) << 4) + row * 128;
            const __half* srcA = wsrc + (size_t)row * NWw + k0 + lu * 8;
            asm volatile("cp.async.cg.shared.global [%0], [%1], 16;"
                         :: "r"(sA + sw), "l"(srcA));
        }
        #pragma unroll
        for (int i = 0; i < 4; i++) {            // B: 64 k-rows x 16 x 16B
            int kr = bkr + i * 16;
            uint32_t dst = sB + kr * 256 + ((bu ^ (kr & 7)) << 4);
            const __half* srcB =
                g_y2 + (size_t)(k0 + kr) * NPIX + p0 + bu * 8;
            asm volatile("cp.async.cg.shared.global [%0], [%1], 16;"
                         :: "r"(dst), "l"(srcB));
        }
        asm volatile("cp.async.commit_group;");
    };

    fill(0, 0);
    for (int kc = 0; kc < 8; kc++) {
        if (kc < 7) fill((kc + 1) & 1, kc + 1);
        if (kc < 7) asm volatile("cp.async.wait_group 1;");
        else        asm volatile("cp.async.wait_group 0;");
        __syncthreads();

        const uint32_t sA = s0 + (kc & 1) * STG_BYTES;
        const uint32_t sB = sA + 16384;

        #pragma unroll
        for (int ks = 0; ks < 4; ks++) {
            uint32_t a[4][4], bf[4][2];
            #pragma unroll
            for (int mi = 0; mi < 4; mi++) {
                int row = wm * 64 + mi * 16 + (lane & 15);
                uint32_t ad = sA + row * 128 + (((ks * 2 + (lane >> 4)) ^ (row & 7)) << 4);
                asm volatile(
                    "ldmatrix.sync.aligned.m8n8.x4.shared.b16 {%0,%1,%2,%3}, [%4];"
                    : "=r"(a[mi][0]), "=r"(a[mi][1]), "=r"(a[mi][2]), "=r"(a[mi][3])
                    : "r"(ad));
            }
            #pragma unroll
            for (int ni = 0; ni < 4; ni++) {
                int kr = ks * 16 + (lane & 15);
                uint32_t uu = wn * 4 + ni;
                uint32_t bd = sB + kr * 256 + ((uu ^ (kr & 7)) << 4);
                asm volatile(
                    "ldmatrix.sync.aligned.m8n8.x2.trans.shared.b16 {%0,%1}, [%2];"
                    : "=r"(bf[ni][0]), "=r"(bf[ni][1]) : "r"(bd));
            }
            #pragma unroll
            for (int mi = 0; mi < 4; mi++)
                #pragma unroll
                for (int ni = 0; ni < 4; ni++)
                    asm volatile(
                        "mma.sync.aligned.m16n8k16.row.col.f32.f16.f16.f32 "
                        "{%0,%1,%2,%3}, {%4,%5,%6,%7}, {%8,%9}, {%0,%1,%2,%3};"
                        : "+f"(acc[mi][ni][0]), "+f"(acc[mi][ni][1]),
                          "+f"(acc[mi][ni][2]), "+f"(acc[mi][ni][3])
                        : "r"(a[mi][0]), "r"(a[mi][1]), "r"(a[mi][2]), "r"(a[mi][3]),
                          "r"(bf[ni][0]), "r"(bf[ni][1]));
        }
        __syncthreads();
    }

    // epilogue: + b1[c] + x residual
    const int bb  = (int)(p0 >> 14);
    const int hw0 = (int)(p0 & 16383) + wn * 32 + (lane & 3) * 2;
    #pragma unroll
    for (int mi = 0; mi < 4; mi++) {
        int cb = mt * 128 + wm * 64 + mi * 16 + (lane >> 2);
        #pragma unroll
        for (int h = 0; h < 2; h++) {
            int c = cb + h * 8;
            float bias = __ldg(b1 + c);
            size_t base = ((size_t)(bb * Cc + c)) * HW + hw0;
            #pragma unroll
            for (int ni = 0; ni < 4; ni++) {
                size_t o = base + ni * 8;
                float2 xv = *(const float2*)(x + o);
                float2 r;
                r.x = acc[mi][ni][h * 2 + 0] + bias + xv.x;
                r.y = acc[mi][ni][h * 2 + 1] + bias + xv.y;
                *(float2*)(out + o) = r;
            }
        }
    }
}

// ---------------------------------------------------------------------------
extern "C" void kernel_launch(void* const* d_in, const int* in_sizes, int n_in,
                              void* d_out, int out_size) {
    const float* x     = (const float*)d_in[0];
    const float* gamma = (const float*)d_in[1];
    const float* beta  = (const float*)d_in[2];
    const float* lbp   = (const float*)d_in[3];
    const float* w1    = (const float*)d_in[4];
    const float* b1    = (const float*)d_in[5];
    float* out = (float*)d_out;

    static bool attr_done = false;
    if (!attr_done) {
        cudaFuncSetAttribute(gemm_kernel,
                             cudaFuncAttributeMaxDynamicSharedMemorySize,
                             2 * STG_BYTES);
        attr_done = true;
    }

    stats_part<<<dim3(Cc, Bn), 256>>>(x);
    finalize_stats<<<1, Cc>>>(gamma, beta);
    w1half<<<(Cc * NWw) / 1024, 256>>>(w1);
    dw_kernel<<<dim3(64, 8, Bn), 256>>>(x, lbp);
    gemm_kernel<<<dim3(2, NPIX / 128), 256, 2 * STG_BYTES>>>(x, b1, out);
}